// round 6
// baseline (speedup 1.0000x reference)
#include <cuda_runtime.h>
#include <cuda_bf16.h>
#include <cstdint>

// ---------------------------------------------------------------------------
// g_Bf: W1 bf16 fragments, coalesced uint4 per (ks, t, lane):
//   index (ks*7 + t)*32 + lane, lane = nrow*4 + q
//   .x = hi(k=ks*16+2q, +1)  .y = hi(k=ks*16+8+2q, +1)
//   .z = lo(...)             .w = lo(...)
//   for n = t*8 + nrow. All 256 CTAs write identical values (benign race).
// ---------------------------------------------------------------------------
static __device__ __align__(16) __nv_bfloat16 g_Bf[32 * 7 * 32 * 8];  // 114688 B

// ---------------- helpers ----------------
__device__ __forceinline__ uint32_t smem_u32(const void* p) {
    uint32_t a;
    asm("{ .reg .u64 t; cvta.to.shared.u64 t, %1; cvt.u32.u64 %0, t; }" : "=r"(a) : "l"(p));
    return a;
}
__device__ __forceinline__ void cp16(uint32_t dst, const float* src) {
    asm volatile("cp.async.cg.shared.global [%0], [%1], 16;" :: "r"(dst), "l"(src) : "memory");
}
__device__ __forceinline__ void cp16z(uint32_t dst, const float* src) {
    asm volatile("cp.async.cg.shared.global [%0], [%1], 16, 0;" :: "r"(dst), "l"(src) : "memory");
}
__device__ __forceinline__ void split2(float vx, float vy, uint32_t& h, uint32_t& l) {
    __nv_bfloat162 hb = __floats2bfloat162_rn(vx, vy);
    float rx = vx - __bfloat162float(hb.x);
    float ry = vy - __bfloat162float(hb.y);
    __nv_bfloat162 lb = __floats2bfloat162_rn(rx, ry);
    h = (uint32_t)__bfloat16_as_ushort(hb.x) | ((uint32_t)__bfloat16_as_ushort(hb.y) << 16);
    l = (uint32_t)__bfloat16_as_ushort(lb.x) | ((uint32_t)__bfloat16_as_ushort(lb.y) << 16);
}
__device__ __forceinline__ uint32_t pack_bf2(__nv_bfloat16 a, __nv_bfloat16 b) {
    return (uint32_t)__bfloat16_as_ushort(a) | ((uint32_t)__bfloat16_as_ushort(b) << 16);
}
__device__ __forceinline__ void mma16816(float* d, uint32_t a0, uint32_t a1,
                                         uint32_t a2, uint32_t a3,
                                         uint32_t b0, uint32_t b1) {
    asm volatile(
        "mma.sync.aligned.m16n8k16.row.col.f32.bf16.bf16.f32 "
        "{%0,%1,%2,%3}, {%4,%5,%6,%7}, {%8,%9}, {%0,%1,%2,%3};"
        : "+f"(d[0]), "+f"(d[1]), "+f"(d[2]), "+f"(d[3])
        : "r"(a0), "r"(a1), "r"(a2), "r"(a3), "r"(b0), "r"(b1));
}

// ---- smem layout (floats) ----
// per-warp x staging: 8 warps x 4 stages x 32 rows x 20 floats = 20480
static constexpr int ROW_F   = 20;                  // 80 B row: aligned + conflict-free
static constexpr int STAGE_F = 32 * ROW_F;          // 640 floats / stage / warp
static constexpr int WARP_F  = 4 * STAGE_F;         // 2560 floats / warp
static constexpr int SX_F    = 8 * WARP_F;          // 20480
static constexpr int O_SL    = SX_F;                // 500
static constexpr int O_SR1   = O_SL + 500;          // 200
static constexpr int O_SRT   = O_SR1 + 200;         // 5000
static constexpr int O_SW2   = O_SRT + 5000;        // 112
static constexpr int O_SB1   = O_SW2 + 112;         // 56
static constexpr int O_SB2   = O_SB1 + 56;          // 2 (+2 pad)
static constexpr int SMEM_F  = O_SB2 + 4;
static constexpr int SMEM_TOTAL = SMEM_F * 4;       // ~105.4 KB

__device__ __forceinline__ void load_warp_chunk(uint32_t wstage_b, const float* xw,
                                                int ks, int lane) {
    #pragma unroll
    for (int i = 0; i < 4; ++i) {
        const int c = lane + 32 * i;
        const int rowl = c >> 2, c4 = c & 3;
        const int kb = ks * 16 + c4 * 4;
        const uint32_t dst = wstage_b + (uint32_t)(rowl * ROW_F + c4 * 4) * 4u;
        if (kb + 4 <= 500) cp16(dst, xw + (size_t)rowl * 500 + kb);
        else               cp16z(dst, xw);
    }
}

// ---------------- single fused kernel ----------------
// 256 threads = 8 warps; warp owns 32 rows x 56 cols, fully autonomous loop.
__global__ void __launch_bounds__(256, 2)
tn_forward(const float* __restrict__ x, float* __restrict__ out,
           const float* __restrict__ A1, const float* __restrict__ A2,
           const float* __restrict__ A3, const float* __restrict__ A4,
           const float* __restrict__ A5, const float* __restrict__ b1,
           const float* __restrict__ B1, const float* __restrict__ B2,
           const float* __restrict__ B3, const float* __restrict__ b2) {
    extern __shared__ float sm[];
    const uint32_t sbase = smem_u32(sm);
    const int tid = threadIdx.x;
    const int warp = tid >> 5, lane = tid & 31;
    const int q = lane & 3, nrow = lane >> 2;

    const size_t row0 = (size_t)blockIdx.x * 256;
    const float* xw = x + (row0 + (size_t)warp * 32) * 500;
    const uint32_t wbase = sbase + (uint32_t)warp * WARP_F * 4u;

    // ---- prefetch 4 stages (warp-local) ----
    #pragma unroll
    for (int s = 0; s < 4; ++s) {
        load_warp_chunk(wbase + s * STAGE_F * 4, xw, s, lane);
        asm volatile("cp.async.commit_group;" ::: "memory");
    }

    // ---- build weights (redundant per CTA, overlaps prefetch) ----
    float* sL  = sm + O_SL;
    float* sR1 = sm + O_SR1;
    float* sRt = sm + O_SRT;
    float* sW2 = sm + O_SW2;
    float* sB1 = sm + O_SB1;
    float* sB2 = sm + O_SB2;

    for (int e = tid; e < 200; e += 256) {
        int xo = e & 1, m = (e >> 1) & 1, l = (e >> 2) % 5, p3 = e / 20;
        float s = 0.f;
        for (int p4 = 0; p4 < 10; ++p4)
            s += A4[((p3 * 5 + l) * 10 + p4) * 2 + xo] * A5[p4 * 2 + m];
        sR1[e] = s;
    }
    for (int e = tid; e < 500; e += 256) {
        int v = e % 5, p2 = (e / 5) % 10, j = (e / 50) % 5, i = e / 250;
        float s = 0.f;
        for (int p1 = 0; p1 < 10; ++p1)
            s += A1[i * 10 + p1] * A2[((p1 * 5 + j) * 10 + p2) * 5 + v];
        sL[e] = s;
    }
    for (int e = tid; e < 56; e += 256) sB1[e] = (e < 50) ? b1[e] : 0.f;
    if (tid < 2) sB2[tid] = b2[tid];
    for (int e = tid; e < 112; e += 256) {
        const int v = e & 1, r = e >> 1;
        float s = 0.f;
        if (r < 50) {
            int i = r / 25, j = (r / 5) % 5, kq2 = r % 5;
            for (int p1 = 0; p1 < 10; ++p1)
                for (int p2 = 0; p2 < 10; ++p2)
                    s += B1[i * 10 + p1] * B2[((p1 * 5 + j) * 10 + p2) * 2 + v] *
                         B3[p2 * 5 + kq2];
        }
        sW2[e] = s;
    }
    __syncthreads();
    for (int e = tid; e < 5000; e += 256) {
        int xo = e & 1, m = (e >> 1) & 1, l = (e >> 2) % 5;
        int w = (e / 20) % 5, k = (e / 100) % 5, p2 = e / 500;
        float s = 0.f;
        for (int p3 = 0; p3 < 10; ++p3)
            s += A3[((p2 * 5 + k) * 10 + p3) * 5 + w] * sR1[((p3 * 5 + l) * 2 + m) * 2 + xo];
        sRt[e] = s;
    }
    __syncthreads();

    // fragments: 7168 uint4, each covering (n, 4 k-values), identical across CTAs
    for (int e = tid; e < 7168; e += 256) {
        const int fl = e & 31, tt = (e >> 5) % 7, ks = e / 224;
        const int fnr = fl >> 2, fq = fl & 3;
        const int n = tt * 8 + fnr;
        __nv_bfloat16 hv[4], lv[4];
        #pragma unroll
        for (int hp = 0; hp < 4; ++hp) {
            const int half = hp >> 1, par = hp & 1;
            const int k = ks * 16 + half * 8 + fq * 2 + par;
            float val = 0.f;
            if (k < 500 && n < 50) {
                int m = k & 1, l = (k >> 1) % 5, kk = (k / 10) % 5, j = (k / 50) % 5,
                    i = k / 250;
                int xo = n & 1, w = (n >> 1) % 5, v = n / 10;
                for (int p2 = 0; p2 < 10; ++p2)
                    val += sL[((i * 5 + j) * 10 + p2) * 5 + v] *
                           sRt[((((p2 * 5 + kk) * 5 + w) * 5 + l) * 2 + m) * 2 + xo];
            }
            hv[hp] = __float2bfloat16(val);
            lv[hp] = __float2bfloat16(val - __bfloat162float(hv[hp]));
        }
        uint4 u;
        u.x = pack_bf2(hv[0], hv[1]);
        u.y = pack_bf2(hv[2], hv[3]);
        u.z = pack_bf2(lv[0], lv[1]);
        u.w = pack_bf2(lv[2], lv[3]);
        reinterpret_cast<uint4*>(g_Bf)[e] = u;
    }
    __syncthreads();

    // ---- main loop: warp-autonomous, no CTA barriers ----
    float acc[2][7][4];
    #pragma unroll
    for (int rb = 0; rb < 2; ++rb)
        #pragma unroll
        for (int t = 0; t < 7; ++t)
            acc[rb][t][0] = acc[rb][t][1] = acc[rb][t][2] = acc[rb][t][3] = 0.f;

    const uint4* Bp = reinterpret_cast<const uint4*>(g_Bf);
    const float* wsx = sm + warp * WARP_F;

    for (int ks = 0; ks < 32; ++ks) {
        uint4 bf[7];
        #pragma unroll
        for (int t = 0; t < 7; ++t)
            bf[t] = Bp[(ks * 7 + t) * 32 + lane];

        asm volatile("cp.async.wait_group 3;" ::: "memory");
        __syncwarp();
        const float* st = wsx + (ks & 3) * STAGE_F;

        #pragma unroll
        for (int rb = 0; rb < 2; ++rb) {
            const int rl = rb * 16 + nrow;  // local rows rl, rl+8
            const float2 u00 = *reinterpret_cast<const float2*>(st + rl * ROW_F + 2 * q);
            const float2 u10 = *reinterpret_cast<const float2*>(st + (rl + 8) * ROW_F + 2 * q);
            const float2 u02 = *reinterpret_cast<const float2*>(st + rl * ROW_F + 8 + 2 * q);
            const float2 u12 = *reinterpret_cast<const float2*>(st + (rl + 8) * ROW_F + 8 + 2 * q);
            uint32_t ah0, ah1, ah2, ah3, al0, al1, al2, al3;
            split2(u00.x, u00.y, ah0, al0);
            split2(u10.x, u10.y, ah1, al1);
            split2(u02.x, u02.y, ah2, al2);
            split2(u12.x, u12.y, ah3, al3);
            #pragma unroll
            for (int t = 0; t < 7; ++t) {
                mma16816(acc[rb][t], ah0, ah1, ah2, ah3, bf[t].x, bf[t].y);  // hi*hi
                mma16816(acc[rb][t], ah0, ah1, ah2, ah3, bf[t].z, bf[t].w);  // hi*lo
                mma16816(acc[rb][t], al0, al1, al2, al3, bf[t].x, bf[t].y);  // lo*hi
            }
        }
        // last mma.sync.aligned converges the warp: all lanes' LDS for this
        // stage are complete before anyone overwrites it below.
        if (ks + 4 < 32)
            load_warp_chunk(wbase + (ks & 3) * STAGE_F * 4, xw, ks + 4, lane);
        asm volatile("cp.async.commit_group;" ::: "memory");
    }

    // ---- epilogue: bias + relu + layer2 (56 -> 2), quad reduce, store ----
    const float b20 = sB2[0], b21 = sB2[1];
    const int kq = q * 2;
    #pragma unroll
    for (int rb = 0; rb < 2; ++rb) {
        float s00 = 0.f, s01 = 0.f, s10 = 0.f, s11 = 0.f;
        #pragma unroll
        for (int t = 0; t < 7; ++t) {
            const int n0 = t * 8 + kq;
            const float2 bv = *reinterpret_cast<const float2*>(sB1 + n0);
            const float4 wv = *reinterpret_cast<const float4*>(sW2 + 2 * n0);
            float h;
            h = fmaxf(acc[rb][t][0] + bv.x, 0.f); s00 = fmaf(h, wv.x, s00); s01 = fmaf(h, wv.y, s01);
            h = fmaxf(acc[rb][t][1] + bv.y, 0.f); s00 = fmaf(h, wv.z, s00); s01 = fmaf(h, wv.w, s01);
            h = fmaxf(acc[rb][t][2] + bv.x, 0.f); s10 = fmaf(h, wv.x, s10); s11 = fmaf(h, wv.y, s11);
            h = fmaxf(acc[rb][t][3] + bv.y, 0.f); s10 = fmaf(h, wv.z, s10); s11 = fmaf(h, wv.w, s11);
        }
        #pragma unroll
        for (int d = 1; d <= 2; d <<= 1) {
            s00 += __shfl_xor_sync(0xffffffffu, s00, d);
            s01 += __shfl_xor_sync(0xffffffffu, s01, d);
            s10 += __shfl_xor_sync(0xffffffffu, s10, d);
            s11 += __shfl_xor_sync(0xffffffffu, s11, d);
        }
        if (q == 0) {
            const size_t r = row0 + warp * 32 + rb * 16 + nrow;
            *reinterpret_cast<float2*>(out + 2 * r) = make_float2(s00 + b20, s01 + b21);
            *reinterpret_cast<float2*>(out + 2 * (r + 8)) = make_float2(s10 + b20, s11 + b21);
        }
    }
}

extern "C" void kernel_launch(void* const* d_in, const int* in_sizes, int n_in,
                              void* d_out, int out_size) {
    cudaFuncSetAttribute(tn_forward, cudaFuncAttributeMaxDynamicSharedMemorySize, SMEM_TOTAL);
    tn_forward<<<256, 256, SMEM_TOTAL>>>(
        (const float*)d_in[0], (float*)d_out,
        (const float*)d_in[1], (const float*)d_in[2], (const float*)d_in[3],
        (const float*)d_in[4], (const float*)d_in[5], (const float*)d_in[6],
        (const float*)d_in[7], (const float*)d_in[8], (const float*)d_in[9],
        (const float*)d_in[10]);
}

// round 7
// speedup vs baseline: 1.2786x; 1.2786x over previous
#include <cuda_runtime.h>
#include <cuda_bf16.h>
#include <cstdint>

// ---------------------------------------------------------------------------
// g_Bf: W1 bf16 fragments, coalesced uint4 per (ks, t, lane):
//   uint4 index (ks*7 + t)*32 + lane, lane = nrow*4 + q, n = t*8 + nrow
//   bf16[half*2+par]   = hi of W1[k = ks*16 + half*8 + q*2 + par][n]
//   bf16[4+half*2+par] = lo
// ---------------------------------------------------------------------------
static __device__ __align__(16) __nv_bfloat16 g_Bf[32 * 7 * 32 * 8];  // 114688 B
static __device__ __align__(16) float g_W2[112];  // [56][2], rows >= 50 zero
static __device__ __align__(8)  float g_b1[56];   // zero-padded
static __device__ __align__(8)  float g_b2[2];

// ---------------- kernel 1: materialize W1/W2/biases from MPO cores ----------
__global__ void build_weights(const float* __restrict__ A1, const float* __restrict__ A2,
                              const float* __restrict__ A3, const float* __restrict__ A4,
                              const float* __restrict__ A5, const float* __restrict__ b1,
                              const float* __restrict__ B1, const float* __restrict__ B2,
                              const float* __restrict__ B3, const float* __restrict__ b2) {
    __shared__ float sL[500];    // [i][j][p2][v]
    __shared__ float sR1[200];   // [p3][l][m][x]
    __shared__ float sRt[5000];  // [p2][k][w][l][m][x]
    const int t = threadIdx.x;

    for (int e = t; e < 200; e += 256) {
        int x = e & 1, m = (e >> 1) & 1, l = (e >> 2) % 5, p3 = e / 20;
        float s = 0.f;
        for (int p4 = 0; p4 < 10; ++p4)
            s += A4[((p3 * 5 + l) * 10 + p4) * 2 + x] * A5[p4 * 2 + m];
        sR1[e] = s;
    }
    for (int e = t; e < 500; e += 256) {
        int v = e % 5, p2 = (e / 5) % 10, j = (e / 50) % 5, i = e / 250;
        float s = 0.f;
        for (int p1 = 0; p1 < 10; ++p1)
            s += A1[i * 10 + p1] * A2[((p1 * 5 + j) * 10 + p2) * 5 + v];
        sL[e] = s;
    }
    __syncthreads();
    for (int e = t; e < 5000; e += 256) {
        int x = e & 1, m = (e >> 1) & 1, l = (e >> 2) % 5;
        int w = (e / 20) % 5, k = (e / 100) % 5, p2 = e / 500;
        float s = 0.f;
        for (int p3 = 0; p3 < 10; ++p3)
            s += A3[((p2 * 5 + k) * 10 + p3) * 5 + w] * sR1[((p3 * 5 + l) * 2 + m) * 2 + x];
        sRt[e] = s;
    }
    __syncthreads();

    const int kbeg = blockIdx.x * 32;   // 16 CTAs cover k 0..511
    for (int e = t; e < 32 * 56; e += 256) {
        const int n = e % 56;
        const int k = kbeg + e / 56;
        float val = 0.f;
        if (k < 500 && n < 50) {
            int m = k & 1, l = (k >> 1) % 5, kk = (k / 10) % 5, j = (k / 50) % 5, i = k / 250;
            int x = n & 1, w = (n >> 1) % 5, v = n / 10;
            for (int p2 = 0; p2 < 10; ++p2)
                val += sL[((i * 5 + j) * 10 + p2) * 5 + v] *
                       sRt[((((p2 * 5 + kk) * 5 + w) * 5 + l) * 2 + m) * 2 + x];
        }
        __nv_bfloat16 hi = __float2bfloat16(val);
        __nv_bfloat16 lo = __float2bfloat16(val - __bfloat162float(hi));
        const int tt = n >> 3, nr = n & 7;
        const int ks = k >> 4, kk16 = k & 15;
        const int half = kk16 >> 3, q = (kk16 >> 1) & 3, par = kk16 & 1;
        const int base = ((ks * 7 + tt) * 32 + (nr * 4 + q)) * 8;
        g_Bf[base + half * 2 + par] = hi;
        g_Bf[base + 4 + half * 2 + par] = lo;
    }

    if (blockIdx.x == 0) {
        for (int e = t; e < 56; e += 256) g_b1[e] = (e < 50) ? b1[e] : 0.f;
        if (t < 2) g_b2[t] = b2[t];
        for (int e = t; e < 112; e += 256) {
            const int v = e & 1, r = e >> 1;
            float s = 0.f;
            if (r < 50) {
                int i = r / 25, j = (r / 5) % 5, kq = r % 5;
                for (int p1 = 0; p1 < 10; ++p1)
                    for (int p2 = 0; p2 < 10; ++p2)
                        s += B1[i * 10 + p1] * B2[((p1 * 5 + j) * 10 + p2) * 2 + v] *
                             B3[p2 * 5 + kq];
            }
            g_W2[e] = s;
        }
    }
}

// ---------------- main kernel helpers ----------------
__device__ __forceinline__ uint32_t smem_u32(const void* p) {
    uint32_t a;
    asm("{ .reg .u64 t; cvta.to.shared.u64 t, %1; cvt.u32.u64 %0, t; }" : "=r"(a) : "l"(p));
    return a;
}
__device__ __forceinline__ void cp16(uint32_t dst, const float* src) {
    asm volatile("cp.async.cg.shared.global [%0], [%1], 16;" :: "r"(dst), "l"(src) : "memory");
}
__device__ __forceinline__ void cp16z(uint32_t dst, const float* src) {
    asm volatile("cp.async.cg.shared.global [%0], [%1], 16, 0;" :: "r"(dst), "l"(src) : "memory");
}
__device__ __forceinline__ void split2(float vx, float vy, uint32_t& h, uint32_t& l) {
    __nv_bfloat162 hb = __floats2bfloat162_rn(vx, vy);
    float rx = vx - __bfloat162float(hb.x);
    float ry = vy - __bfloat162float(hb.y);
    __nv_bfloat162 lb = __floats2bfloat162_rn(rx, ry);
    h = (uint32_t)__bfloat16_as_ushort(hb.x) | ((uint32_t)__bfloat16_as_ushort(hb.y) << 16);
    l = (uint32_t)__bfloat16_as_ushort(lb.x) | ((uint32_t)__bfloat16_as_ushort(lb.y) << 16);
}
__device__ __forceinline__ void mma16816(float* d, uint32_t a0, uint32_t a1,
                                         uint32_t a2, uint32_t a3,
                                         uint32_t b0, uint32_t b1) {
    asm volatile(
        "mma.sync.aligned.m16n8k16.row.col.f32.bf16.bf16.f32 "
        "{%0,%1,%2,%3}, {%4,%5,%6,%7}, {%8,%9}, {%0,%1,%2,%3};"
        : "+f"(d[0]), "+f"(d[1]), "+f"(d[2]), "+f"(d[3])
        : "r"(a0), "r"(a1), "r"(a2), "r"(a3), "r"(b0), "r"(b1));
}

// per-warp x staging: 8 warps x 5 stages x 32 rows x 20 floats
static constexpr int ROW_F   = 20;              // 80 B: aligned + conflict-free banks
static constexpr int STAGES  = 5;
static constexpr int STAGE_F = 32 * ROW_F;      // 640 floats / stage / warp
static constexpr int WARP_F  = STAGES * STAGE_F;
static constexpr int SMEM_TOTAL = 8 * WARP_F * 4;  // 102400 B

__device__ __forceinline__ void load_warp_chunk(uint32_t wstage_b, const float* xw,
                                                int ks, int lane) {
    #pragma unroll
    for (int i = 0; i < 4; ++i) {
        const int c = lane + 32 * i;
        const int rowl = c >> 2, c4 = c & 3;
        const int kb = ks * 16 + c4 * 4;
        const uint32_t dst = wstage_b + (uint32_t)(rowl * ROW_F + c4 * 4) * 4u;
        if (kb + 4 <= 500) cp16(dst, xw + (size_t)rowl * 500 + kb);
        else               cp16z(dst, xw);
    }
}

// ---------------- kernel 2: fused forward ----------------
// 256 threads = 8 warps; warp owns 32 rows x 56 cols, fully autonomous loop
// (no CTA barriers in the mainloop).
__global__ void __launch_bounds__(256, 2)
tn_forward(const float* __restrict__ x, float* __restrict__ out) {
    extern __shared__ float sm[];
    const uint32_t sbase = smem_u32(sm);
    const int tid = threadIdx.x;
    const int warp = tid >> 5, lane = tid & 31;
    const int q = lane & 3, nrow = lane >> 2;

    const size_t row0 = (size_t)blockIdx.x * 256;
    const float* xw = x + (row0 + (size_t)warp * 32) * 500;
    const uint32_t wbase = sbase + (uint32_t)warp * WARP_F * 4u;

    // prefetch STAGES stages (warp-local)
    #pragma unroll
    for (int s = 0; s < STAGES; ++s) {
        load_warp_chunk(wbase + s * STAGE_F * 4, xw, s, lane);
        asm volatile("cp.async.commit_group;" ::: "memory");
    }

    float acc[2][7][4];
    #pragma unroll
    for (int rb = 0; rb < 2; ++rb)
        #pragma unroll
        for (int t = 0; t < 7; ++t)
            acc[rb][t][0] = acc[rb][t][1] = acc[rb][t][2] = acc[rb][t][3] = 0.f;

    const uint4* Bp = reinterpret_cast<const uint4*>(g_Bf);
    const float* wsx = sm + warp * WARP_F;

    int stg = 0;
    for (int ks = 0; ks < 32; ++ks) {
        uint4 bf[7];
        #pragma unroll
        for (int t = 0; t < 7; ++t)
            bf[t] = __ldg(&Bp[(ks * 7 + t) * 32 + lane]);

        asm volatile("cp.async.wait_group %0;" :: "n"(STAGES - 1) : "memory");
        __syncwarp();
        const float* st = wsx + stg * STAGE_F;

        #pragma unroll
        for (int rb = 0; rb < 2; ++rb) {
            const int rl = rb * 16 + nrow;  // local rows rl, rl+8
            const float2 u00 = *reinterpret_cast<const float2*>(st + rl * ROW_F + 2 * q);
            const float2 u10 = *reinterpret_cast<const float2*>(st + (rl + 8) * ROW_F + 2 * q);
            const float2 u02 = *reinterpret_cast<const float2*>(st + rl * ROW_F + 8 + 2 * q);
            const float2 u12 = *reinterpret_cast<const float2*>(st + (rl + 8) * ROW_F + 8 + 2 * q);
            uint32_t ah0, ah1, ah2, ah3, al0, al1, al2, al3;
            split2(u00.x, u00.y, ah0, al0);
            split2(u10.x, u10.y, ah1, al1);
            split2(u02.x, u02.y, ah2, al2);
            split2(u12.x, u12.y, ah3, al3);
            #pragma unroll
            for (int t = 0; t < 7; ++t) {
                mma16816(acc[rb][t], ah0, ah1, ah2, ah3, bf[t].x, bf[t].y);  // hi*hi
                mma16816(acc[rb][t], ah0, ah1, ah2, ah3, bf[t].z, bf[t].w);  // hi*lo
                mma16816(acc[rb][t], al0, al1, al2, al3, bf[t].x, bf[t].y);  // lo*hi
            }
        }
        // mma.sync convergence guarantees all lanes finished this stage's LDS
        // before the refill below overwrites it.
        if (ks + STAGES < 32)
            load_warp_chunk(wbase + stg * STAGE_F * 4, xw, ks + STAGES, lane);
        asm volatile("cp.async.commit_group;" ::: "memory");
        stg = (stg + 1 == STAGES) ? 0 : stg + 1;
    }

    // epilogue: bias + relu + layer2 (56 -> 2), quad reduce, store
    const float b20 = g_b2[0], b21 = g_b2[1];
    const int kq = q * 2;
    #pragma unroll
    for (int rb = 0; rb < 2; ++rb) {
        float s00 = 0.f, s01 = 0.f, s10 = 0.f, s11 = 0.f;
        #pragma unroll
        for (int t = 0; t < 7; ++t) {
            const int n0 = t * 8 + kq;
            const float2 bv = *reinterpret_cast<const float2*>(g_b1 + n0);
            const float4 wv = *reinterpret_cast<const float4*>(g_W2 + 2 * n0);
            float h;
            h = fmaxf(acc[rb][t][0] + bv.x, 0.f); s00 = fmaf(h, wv.x, s00); s01 = fmaf(h, wv.y, s01);
            h = fmaxf(acc[rb][t][1] + bv.y, 0.f); s00 = fmaf(h, wv.z, s00); s01 = fmaf(h, wv.w, s01);
            h = fmaxf(acc[rb][t][2] + bv.x, 0.f); s10 = fmaf(h, wv.x, s10); s11 = fmaf(h, wv.y, s11);
            h = fmaxf(acc[rb][t][3] + bv.y, 0.f); s10 = fmaf(h, wv.z, s10); s11 = fmaf(h, wv.w, s11);
        }
        #pragma unroll
        for (int d = 1; d <= 2; d <<= 1) {
            s00 += __shfl_xor_sync(0xffffffffu, s00, d);
            s01 += __shfl_xor_sync(0xffffffffu, s01, d);
            s10 += __shfl_xor_sync(0xffffffffu, s10, d);
            s11 += __shfl_xor_sync(0xffffffffu, s11, d);
        }
        if (q == 0) {
            const size_t r = row0 + warp * 32 + rb * 16 + nrow;
            *reinterpret_cast<float2*>(out + 2 * r) = make_float2(s00 + b20, s01 + b21);
            *reinterpret_cast<float2*>(out + 2 * (r + 8)) = make_float2(s10 + b20, s11 + b21);
        }
    }
}

extern "C" void kernel_launch(void* const* d_in, const int* in_sizes, int n_in,
                              void* d_out, int out_size) {
    const float* x = (const float*)d_in[0];
    build_weights<<<16, 256>>>(
        (const float*)d_in[1], (const float*)d_in[2], (const float*)d_in[3],
        (const float*)d_in[4], (const float*)d_in[5], (const float*)d_in[6],
        (const float*)d_in[7], (const float*)d_in[8], (const float*)d_in[9],
        (const float*)d_in[10]);
    cudaFuncSetAttribute(tn_forward, cudaFuncAttributeMaxDynamicSharedMemorySize, SMEM_TOTAL);
    tn_forward<<<256, 256, SMEM_TOTAL>>>(x, (float*)d_out);
}

// round 8
// speedup vs baseline: 1.4284x; 1.1171x over previous
#include <cuda_runtime.h>
#include <cuda_bf16.h>
#include <cstdint>

// ---------------------------------------------------------------------------
// g_Bf: W1 bf16 fragments, coalesced uint4 per (ks, t, lane):
//   uint4 index (ks*7 + t)*32 + lane, lane = nrow*4 + q, n = t*8 + nrow
//   bf16[half*2+par]   = hi of W1[k = ks*16 + half*8 + q*2 + par][n]
//   bf16[4+half*2+par] = lo
// ---------------------------------------------------------------------------
static __device__ __align__(16) __nv_bfloat16 g_Bf[32 * 7 * 32 * 8];  // 114688 B
static __device__ __align__(16) float g_W2[112];  // [56][2], rows >= 50 zero
static __device__ __align__(8)  float g_b1[56];   // zero-padded
static __device__ __align__(8)  float g_b2[2];

// ---------------- kernel 1: materialize W1/W2/biases from MPO cores ----------
// 64 CTAs, each fills 8 k-rows of the padded 512x56 W1 fragment table.
__global__ void build_weights(const float* __restrict__ A1, const float* __restrict__ A2,
                              const float* __restrict__ A3, const float* __restrict__ A4,
                              const float* __restrict__ A5, const float* __restrict__ b1,
                              const float* __restrict__ B1, const float* __restrict__ B2,
                              const float* __restrict__ B3, const float* __restrict__ b2) {
    __shared__ float sL[500];    // [i][j][p2][v]
    __shared__ float sR1[200];   // [p3][l][m][x]
    __shared__ float sRt[5000];  // [p2][k][w][l][m][x]
    const int t = threadIdx.x;

    for (int e = t; e < 200; e += 256) {
        int x = e & 1, m = (e >> 1) & 1, l = (e >> 2) % 5, p3 = e / 20;
        float s = 0.f;
        for (int p4 = 0; p4 < 10; ++p4)
            s += A4[((p3 * 5 + l) * 10 + p4) * 2 + x] * A5[p4 * 2 + m];
        sR1[e] = s;
    }
    for (int e = t; e < 500; e += 256) {
        int v = e % 5, p2 = (e / 5) % 10, j = (e / 50) % 5, i = e / 250;
        float s = 0.f;
        for (int p1 = 0; p1 < 10; ++p1)
            s += A1[i * 10 + p1] * A2[((p1 * 5 + j) * 10 + p2) * 5 + v];
        sL[e] = s;
    }
    __syncthreads();
    for (int e = t; e < 5000; e += 256) {
        int x = e & 1, m = (e >> 1) & 1, l = (e >> 2) % 5;
        int w = (e / 20) % 5, k = (e / 100) % 5, p2 = e / 500;
        float s = 0.f;
        for (int p3 = 0; p3 < 10; ++p3)
            s += A3[((p2 * 5 + k) * 10 + p3) * 5 + w] * sR1[((p3 * 5 + l) * 2 + m) * 2 + x];
        sRt[e] = s;
    }
    __syncthreads();

    const int kbeg = blockIdx.x * 8;   // 64 CTAs cover k 0..511
    for (int e = t; e < 8 * 56; e += 256) {
        const int n = e % 56;
        const int k = kbeg + e / 56;
        float val = 0.f;
        if (k < 500 && n < 50) {
            int m = k & 1, l = (k >> 1) % 5, kk = (k / 10) % 5, j = (k / 50) % 5, i = k / 250;
            int x = n & 1, w = (n >> 1) % 5, v = n / 10;
            for (int p2 = 0; p2 < 10; ++p2)
                val += sL[((i * 5 + j) * 10 + p2) * 5 + v] *
                       sRt[((((p2 * 5 + kk) * 5 + w) * 5 + l) * 2 + m) * 2 + x];
        }
        __nv_bfloat16 hi = __float2bfloat16(val);
        __nv_bfloat16 lo = __float2bfloat16(val - __bfloat162float(hi));
        const int tt = n >> 3, nr = n & 7;
        const int ks = k >> 4, kk16 = k & 15;
        const int half = kk16 >> 3, q = (kk16 >> 1) & 3, par = kk16 & 1;
        const int base = ((ks * 7 + tt) * 32 + (nr * 4 + q)) * 8;
        g_Bf[base + half * 2 + par] = hi;
        g_Bf[base + 4 + half * 2 + par] = lo;
    }

    if (blockIdx.x == 0) {
        for (int e = t; e < 56; e += 256) g_b1[e] = (e < 50) ? b1[e] : 0.f;
        if (t < 2) g_b2[t] = b2[t];
        for (int e = t; e < 112; e += 256) {
            const int v = e & 1, r = e >> 1;
            float s = 0.f;
            if (r < 50) {
                int i = r / 25, j = (r / 5) % 5, kq = r % 5;
                for (int p1 = 0; p1 < 10; ++p1)
                    for (int p2 = 0; p2 < 10; ++p2)
                        s += B1[i * 10 + p1] * B2[((p1 * 5 + j) * 10 + p2) * 2 + v] *
                             B3[p2 * 5 + kq];
            }
            g_W2[e] = s;
        }
    }
}

// ---------------- main kernel helpers ----------------
__device__ __forceinline__ uint32_t smem_u32(const void* p) {
    uint32_t a;
    asm("{ .reg .u64 t; cvta.to.shared.u64 t, %1; cvt.u32.u64 %0, t; }" : "=r"(a) : "l"(p));
    return a;
}
__device__ __forceinline__ void cp16(uint32_t dst, const void* src) {
    asm volatile("cp.async.cg.shared.global [%0], [%1], 16;" :: "r"(dst), "l"(src) : "memory");
}
__device__ __forceinline__ void cp16z(uint32_t dst, const void* src) {
    asm volatile("cp.async.cg.shared.global [%0], [%1], 16, 0;" :: "r"(dst), "l"(src) : "memory");
}
__device__ __forceinline__ void split2(float vx, float vy, uint32_t& h, uint32_t& l) {
    __nv_bfloat162 hb = __floats2bfloat162_rn(vx, vy);
    float rx = vx - __bfloat162float(hb.x);
    float ry = vy - __bfloat162float(hb.y);
    __nv_bfloat162 lb = __floats2bfloat162_rn(rx, ry);
    h = (uint32_t)__bfloat16_as_ushort(hb.x) | ((uint32_t)__bfloat16_as_ushort(hb.y) << 16);
    l = (uint32_t)__bfloat16_as_ushort(lb.x) | ((uint32_t)__bfloat16_as_ushort(lb.y) << 16);
}
__device__ __forceinline__ void mma16816(float* d, uint32_t a0, uint32_t a1,
                                         uint32_t a2, uint32_t a3,
                                         uint32_t b0, uint32_t b1) {
    asm volatile(
        "mma.sync.aligned.m16n8k16.row.col.f32.bf16.bf16.f32 "
        "{%0,%1,%2,%3}, {%4,%5,%6,%7}, {%8,%9}, {%0,%1,%2,%3};"
        : "+f"(d[0]), "+f"(d[1]), "+f"(d[2]), "+f"(d[3])
        : "r"(a0), "r"(a1), "r"(a2), "r"(a3), "r"(b0), "r"(b1));
}

// ---- smem layout ----
// x: per-warp 3-stage ring, 32 rows x 20 floats per stage (conflict-free pad).
// B: CTA-shared 3-stage ring, 3584 B (= 7 tiles x 32 uint4) per stage.
static constexpr int ROW_F   = 20;
static constexpr int STAGES  = 3;
static constexpr int STAGE_F = 32 * ROW_F;              // 640 floats
static constexpr int XW_F    = STAGES * STAGE_F;        // per-warp floats
static constexpr int O_B_F   = 8 * XW_F;                // 15360
static constexpr int BSTG_F  = 896;                     // 3584 B per B stage
static constexpr int SMEM_TOTAL = (O_B_F + STAGES * BSTG_F) * 4;  // 72192 B

__device__ __forceinline__ void load_x_chunk(uint32_t wstage_b, const float* xw,
                                             int ks, int lane) {
    #pragma unroll
    for (int i = 0; i < 4; ++i) {
        const int c = lane + 32 * i;
        const int rowl = c >> 2, c4 = c & 3;
        const int kb = ks * 16 + c4 * 4;
        const uint32_t dst = wstage_b + (uint32_t)(rowl * ROW_F + c4 * 4) * 4u;
        if (kb + 4 <= 500) cp16(dst, xw + (size_t)rowl * 500 + kb);
        else               cp16z(dst, xw);
    }
}

// ---------------- kernel 2: fused forward ----------------
// 256 threads = 8 warps; warp owns 32 rows x 56 cols.
// One __syncthreads per k-step; chunk ks+S-1 is fetched into the slot
// consumed at iteration ks-1 (already fenced by this iteration's barrier).
__global__ void __launch_bounds__(256, 2)
tn_forward(const float* __restrict__ x, float* __restrict__ out) {
    extern __shared__ float sm[];
    const uint32_t sbase = smem_u32(sm);
    const int tid = threadIdx.x;
    const int warp = tid >> 5, lane = tid & 31;
    const int q = lane & 3, nrow = lane >> 2;

    const size_t row0 = (size_t)blockIdx.x * 256;
    const float* xw = x + (row0 + (size_t)warp * 32) * 500;
    const uint32_t xwbase = sbase + (uint32_t)warp * XW_F * 4u;
    const uint32_t bbase = sbase + (uint32_t)O_B_F * 4u;
    const char* gB = reinterpret_cast<const char*>(g_Bf);

    // prologue: fetch chunks 0..S-2 into slots 0..S-2
    #pragma unroll
    for (int s = 0; s < STAGES - 1; ++s) {
        load_x_chunk(xwbase + s * STAGE_F * 4, xw, s, lane);
        if (tid < 224) cp16(bbase + s * BSTG_F * 4 + tid * 16, gB + s * 3584 + tid * 16);
        asm volatile("cp.async.commit_group;" ::: "memory");
    }

    float acc[2][7][4];
    #pragma unroll
    for (int rb = 0; rb < 2; ++rb)
        #pragma unroll
        for (int t = 0; t < 7; ++t)
            acc[rb][t][0] = acc[rb][t][1] = acc[rb][t][2] = acc[rb][t][3] = 0.f;

    const float* wsx = sm + warp * XW_F;

    for (int ks = 0; ks < 32; ++ks) {
        const int slot = ks % STAGES;
        asm volatile("cp.async.wait_group %0;" :: "n"(STAGES - 2) : "memory");
        __syncthreads();

        // fetch chunk ks+S-1 into slot (ks+S-1) mod S == (ks-1) mod S
        const int c = ks + STAGES - 1;
        if (c < 32) {
            const int fslot = c % STAGES;
            load_x_chunk(xwbase + fslot * STAGE_F * 4, xw, c, lane);
            if (tid < 224)
                cp16(bbase + fslot * BSTG_F * 4 + tid * 16, gB + c * 3584 + tid * 16);
        }
        asm volatile("cp.async.commit_group;" ::: "memory");

        // consume: B from shared (LDS.128, conflict-free)
        const uint4* bst = reinterpret_cast<const uint4*>(sm + O_B_F + slot * BSTG_F);
        uint4 bf[7];
        #pragma unroll
        for (int t = 0; t < 7; ++t)
            bf[t] = bst[t * 32 + lane];

        const float* st = wsx + slot * STAGE_F;
        #pragma unroll
        for (int rb = 0; rb < 2; ++rb) {
            const int rl = rb * 16 + nrow;
            const float2 u00 = *reinterpret_cast<const float2*>(st + rl * ROW_F + 2 * q);
            const float2 u10 = *reinterpret_cast<const float2*>(st + (rl + 8) * ROW_F + 2 * q);
            const float2 u02 = *reinterpret_cast<const float2*>(st + rl * ROW_F + 8 + 2 * q);
            const float2 u12 = *reinterpret_cast<const float2*>(st + (rl + 8) * ROW_F + 8 + 2 * q);
            uint32_t ah0, ah1, ah2, ah3, al0, al1, al2, al3;
            split2(u00.x, u00.y, ah0, al0);
            split2(u10.x, u10.y, ah1, al1);
            split2(u02.x, u02.y, ah2, al2);
            split2(u12.x, u12.y, ah3, al3);
            #pragma unroll
            for (int t = 0; t < 7; ++t) {
                mma16816(acc[rb][t], ah0, ah1, ah2, ah3, bf[t].x, bf[t].y);  // hi*hi
                mma16816(acc[rb][t], ah0, ah1, ah2, ah3, bf[t].z, bf[t].w);  // hi*lo
                mma16816(acc[rb][t], al0, al1, al2, al3, bf[t].x, bf[t].y);  // lo*hi
            }
        }
    }

    // epilogue: bias + relu + layer2 (56 -> 2), quad reduce, store
    const float b20 = g_b2[0], b21 = g_b2[1];
    const int kq = q * 2;
    #pragma unroll
    for (int rb = 0; rb < 2; ++rb) {
        float s00 = 0.f, s01 = 0.f, s10 = 0.f, s11 = 0.f;
        #pragma unroll
        for (int t = 0; t < 7; ++t) {
            const int n0 = t * 8 + kq;
            const float2 bv = *reinterpret_cast<const float2*>(g_b1 + n0);
            const float4 wv = *reinterpret_cast<const float4*>(g_W2 + 2 * n0);
            float h;
            h = fmaxf(acc[rb][t][0] + bv.x, 0.f); s00 = fmaf(h, wv.x, s00); s01 = fmaf(h, wv.y, s01);
            h = fmaxf(acc[rb][t][1] + bv.y, 0.f); s00 = fmaf(h, wv.z, s00); s01 = fmaf(h, wv.w, s01);
            h = fmaxf(acc[rb][t][2] + bv.x, 0.f); s10 = fmaf(h, wv.x, s10); s11 = fmaf(h, wv.y, s11);
            h = fmaxf(acc[rb][t][3] + bv.y, 0.f); s10 = fmaf(h, wv.z, s10); s11 = fmaf(h, wv.w, s11);
        }
        #pragma unroll
        for (int d = 1; d <= 2; d <<= 1) {
            s00 += __shfl_xor_sync(0xffffffffu, s00, d);
            s01 += __shfl_xor_sync(0xffffffffu, s01, d);
            s10 += __shfl_xor_sync(0xffffffffu, s10, d);
            s11 += __shfl_xor_sync(0xffffffffu, s11, d);
        }
        if (q == 0) {
            const size_t r = row0 + warp * 32 + rb * 16 + nrow;
            *reinterpret_cast<float2*>(out + 2 * r) = make_float2(s00 + b20, s01 + b21);
            *reinterpret_cast<float2*>(out + 2 * (r + 8)) = make_float2(s10 + b20, s11 + b21);
        }
    }
}

extern "C" void kernel_launch(void* const* d_in, const int* in_sizes, int n_in,
                              void* d_out, int out_size) {
    const float* x = (const float*)d_in[0];
    build_weights<<<64, 256>>>(
        (const float*)d_in[1], (const float*)d_in[2], (const float*)d_in[3],
        (const float*)d_in[4], (const float*)d_in[5], (const float*)d_in[6],
        (const float*)d_in[7], (const float*)d_in[8], (const float*)d_in[9],
        (const float*)d_in[10]);
    cudaFuncSetAttribute(tn_forward, cudaFuncAttributeMaxDynamicSharedMemorySize, SMEM_TOTAL);
    tn_forward<<<256, 256, SMEM_TOTAL>>>(x, (float*)d_out);
}